// round 1
// baseline (speedup 1.0000x reference)
#include <cuda_runtime.h>

#define NQ 12
#define DIM 4096
#define NTHREADS 256

// Fused per-(layer,qubit) unitaries U = RZ(c) * RX(b) * RY(a), 2x2 complex.
__device__ float2 g_U[3][12][4];

__device__ __forceinline__ float2 cmul(float2 a, float2 b) {
    return make_float2(a.x * b.x - a.y * b.y, a.x * b.y + a.y * b.x);
}

__global__ void precompute_U_kernel(const float* __restrict__ params) {
    int i = threadIdx.x;            // 0..35 -> (layer, q)
    if (i >= 36) return;
    int layer = i / 12, q = i % 12;
    const float* p = params + i * 3;   // params[layer][q][{ry,rx,rz}]
    float sa, ca; sincosf(0.5f * p[0], &sa, &ca);
    float sb, cb; sincosf(0.5f * p[1], &sb, &cb);
    float sc, cc; sincosf(0.5f * p[2], &sc, &cc);
    // M = RX(b) * RY(a)
    float2 m00 = make_float2( cb * ca, -sb * sa);
    float2 m01 = make_float2(-cb * sa, -sb * ca);
    float2 m10 = make_float2( cb * sa, -sb * ca);
    float2 m11 = make_float2( cb * ca,  sb * sa);
    // U = RZ(c) * M : row0 *= e^{-ic/2}, row1 *= e^{+ic/2}
    float2 e0 = make_float2(cc, -sc);
    float2 e1 = make_float2(cc,  sc);
    g_U[layer][q][0] = cmul(e0, m00);
    g_U[layer][q][1] = cmul(e0, m01);
    g_U[layer][q][2] = cmul(e1, m10);
    g_U[layer][q][3] = cmul(e1, m11);
}

// Padded shared address: +1 float per 16 to avoid stride-16 bank conflicts.
__device__ __forceinline__ int padidx(int n) { return n + (n >> 4); }

// Apply 4 single-qubit gates (global bits basebit..basebit+3) to the 16
// amplitudes of this thread's group (base + k*stride, k=0..15), in registers.
__device__ __forceinline__ void do_pass(float* sre, float* sim,
                                        const float2 (*sUl)[4],
                                        int base, int stride, int basebit)
{
    float vr[16], vi[16];
#pragma unroll
    for (int k = 0; k < 16; ++k) {
        int pn = padidx(base + k * stride);
        vr[k] = sre[pn]; vi[k] = sim[pn];
    }
#pragma unroll
    for (int m = 0; m < 4; ++m) {
        // global bit p = basebit + m  <->  wire = 11 - p
        const float2* u = sUl[11 - basebit - m];
        float2 u00 = u[0], u01 = u[1], u10 = u[2], u11 = u[3];
#pragma unroll
        for (int k = 0; k < 16; ++k) {
            if (k & (1 << m)) continue;
            int k1 = k | (1 << m);
            float ar = vr[k], ai = vi[k], br = vr[k1], bi = vi[k1];
            vr[k]  = u00.x * ar - u00.y * ai + u01.x * br - u01.y * bi;
            vi[k]  = u00.x * ai + u00.y * ar + u01.x * bi + u01.y * br;
            vr[k1] = u10.x * ar - u10.y * ai + u11.x * br - u11.y * bi;
            vi[k1] = u10.x * ai + u10.y * ar + u11.x * bi + u11.y * br;
        }
    }
#pragma unroll
    for (int k = 0; k < 16; ++k) {
        int pn = padidx(base + k * stride);
        sre[pn] = vr[k]; sim[pn] = vi[k];
    }
}

__global__ __launch_bounds__(NTHREADS)
void qnn_kernel(const float* __restrict__ x, float* __restrict__ out)
{
    __shared__ float sre[DIM + DIM / 16];
    __shared__ float sim[DIM + DIM / 16];
    __shared__ float2 sU[3][12][4];
    __shared__ float scw[NQ], ssw[NQ];

    const int tid = threadIdx.x;
    const int b = blockIdx.x;

    if (tid < NQ) {
        float s, c; sincosf(0.5f * x[b * NQ + tid], &s, &c);
        scw[tid] = c; ssw[tid] = s;
    }
    if (tid < 3 * 12 * 4) ((float2*)sU)[tid] = ((const float2*)g_U)[tid];
    __syncthreads();

    // ---- init: product state from RY(x) on |0..0>, purely real ----
    // index n: wire w <-> bit (11-w). n = tid + k*256: wires 4..11 from tid,
    // wires 0..3 from k.
    float phi = 1.0f;
#pragma unroll
    for (int w = 4; w < 12; ++w)
        phi *= ((tid >> (11 - w)) & 1) ? ssw[w] : scw[w];
#pragma unroll
    for (int k = 0; k < 16; ++k) {
        float a = phi;
#pragma unroll
        for (int w = 0; w < 4; ++w)
            a *= ((k >> (3 - w)) & 1) ? ssw[w] : scw[w];
        int pn = padidx(tid + (k << 8));
        sre[pn] = a; sim[pn] = 0.0f;
    }
    __syncthreads();

#pragma unroll 1
    for (int layer = 0; layer < 3; ++layer) {
        // 12 fused single-qubit gates in 3 radix-16 passes (gates commute)
        do_pass(sre, sim, sU[layer], tid << 4, 1, 0);
        __syncthreads();
        do_pass(sre, sim, sU[layer], (tid & 15) | ((tid >> 4) << 8), 16, 4);
        __syncthreads();
        do_pass(sre, sim, sU[layer], tid, 256, 8);
        __syncthreads();

        // ---- CNOT chain (ctrl q=0..10) == Gray-code gather ----
        // new[j] = old[j ^ (j >> 1)]
        float tr[16], ti[16];
#pragma unroll
        for (int k = 0; k < 16; ++k) {
            int j = tid + (k << 8);
            int g = j ^ (j >> 1);
            int pg = padidx(g);
            tr[k] = sre[pg]; ti[k] = sim[pg];
        }
        __syncthreads();
#pragma unroll
        for (int k = 0; k < 16; ++k) {
            int pj = padidx(tid + (k << 8));
            sre[pj] = tr[k]; sim[pj] = ti[k];
        }
        __syncthreads();
    }

    if (tid == 0) {
        float r0 = sre[padidx(0)], i0 = sim[padidx(0)];
        float r1 = sre[padidx(1)], i1 = sim[padidx(1)];
        float p0 = r0 * r0 + i0 * i0;
        float p1 = r1 * r1 + i1 * i1;
        float inv = 1.0f / (p0 + p1);
        out[b * 2 + 0] = p0 * inv;
        out[b * 2 + 1] = p1 * inv;
    }
}

extern "C" void kernel_launch(void* const* d_in, const int* in_sizes, int n_in,
                              void* d_out, int out_size) {
    const float* x      = (const float*)d_in[0];  // (B, 12) float32
    const float* params = (const float*)d_in[1];  // (3, 12, 3) float32
    float* out = (float*)d_out;                   // (B, 2) float32
    int B = in_sizes[0] / NQ;

    precompute_U_kernel<<<1, 64>>>(params);
    qnn_kernel<<<B, NTHREADS>>>(x, out);
}

// round 2
// speedup vs baseline: 1.5799x; 1.5799x over previous
#include <cuda_runtime.h>

#define NQ 12
#define DIM 4096
#define NTHREADS 256
#define PADDED (DIM + DIM / 16)   // 4352

typedef unsigned long long ull;

// Fused per-(layer,qubit) unitaries U = RZ(c) * RX(b) * RY(a), 2x2 complex.
__device__ float2 g_U[3][12][4];

__device__ __forceinline__ float2 cmulc(float2 a, float2 b) {
    return make_float2(a.x * b.x - a.y * b.y, a.x * b.y + a.y * b.x);
}

__global__ void precompute_U_kernel(const float* __restrict__ params) {
    int i = threadIdx.x;            // 0..35 -> (layer, q)
    if (i >= 36) return;
    int layer = i / 12, q = i % 12;
    const float* p = params + i * 3;   // params[layer][q][{ry,rx,rz}]
    float sa, ca; sincosf(0.5f * p[0], &sa, &ca);
    float sb, cb; sincosf(0.5f * p[1], &sb, &cb);
    float sc, cc; sincosf(0.5f * p[2], &sc, &cc);
    // M = RX(b) * RY(a)
    float2 m00 = make_float2( cb * ca, -sb * sa);
    float2 m01 = make_float2(-cb * sa, -sb * ca);
    float2 m10 = make_float2( cb * sa, -sb * ca);
    float2 m11 = make_float2( cb * ca,  sb * sa);
    // U = RZ(c) * M : row0 *= e^{-ic/2}, row1 *= e^{+ic/2}
    float2 e0 = make_float2(cc, -sc);
    float2 e1 = make_float2(cc,  sc);
    g_U[layer][q][0] = cmulc(e0, m00);
    g_U[layer][q][1] = cmulc(e0, m01);
    g_U[layer][q][2] = cmulc(e1, m10);
    g_U[layer][q][3] = cmulc(e1, m11);
}

// ---- packed f32x2 helpers (lane0 = batch b0, lane1 = batch b1) ----
__device__ __forceinline__ ull pack2(float lo, float hi) {
    ull r; asm("mov.b64 %0, {%1, %2};" : "=l"(r) : "f"(lo), "f"(hi)); return r;
}
__device__ __forceinline__ ull bcast2(float v) { return pack2(v, v); }
__device__ __forceinline__ void unpack2(ull v, float& lo, float& hi) {
    asm("mov.b64 {%0, %1}, %2;" : "=f"(lo), "=f"(hi) : "l"(v));
}
__device__ __forceinline__ ull fma2(ull a, ull b, ull c) {
    ull d; asm("fma.rn.f32x2 %0, %1, %2, %3;" : "=l"(d) : "l"(a), "l"(b), "l"(c)); return d;
}
__device__ __forceinline__ ull mul2(ull a, ull b) {
    ull d; asm("mul.rn.f32x2 %0, %1, %2;" : "=l"(d) : "l"(a), "l"(b)); return d;
}

// Padded shared index: +1 slot per 16 to kill stride-16/256 bank conflicts.
__device__ __forceinline__ int padidx(int n) { return n + (n >> 4); }

// Inverse Gray code (prefix XOR): gray(grayinv(i)) == i, 12 bits.
__device__ __forceinline__ int grayinv(int i) {
    i ^= i >> 1; i ^= i >> 2; i ^= i >> 4; i ^= i >> 8;
    return i;
}

// Apply 4 single-qubit gates (global bits basebit..basebit+3) to the 16
// packed amplitudes at base + k*stride. LOAD: fetch from shared first.
// GRAY: write back through the CNOT-chain permutation new[grayinv(i)] = v[i].
template<bool LOAD, bool GRAY>
__device__ __forceinline__ void gate_pass(ull* sre, ull* sim,
                                          const float2 (*sUl)[4],
                                          int base, int stride, int basebit,
                                          ull* vr, ull* vi)
{
    if (LOAD) {
#pragma unroll
        for (int k = 0; k < 16; ++k) {
            int pn = padidx(base + k * stride);
            vr[k] = sre[pn]; vi[k] = sim[pn];
        }
    }
#pragma unroll
    for (int m = 0; m < 4; ++m) {
        // global bit p = basebit + m  <->  wire = 11 - p
        const float2* u = sUl[11 - basebit - m];
        float2 u0 = u[0], u1 = u[1], u2 = u[2], u3 = u[3];
        ull u00x = bcast2(u0.x), u00y = bcast2(u0.y), n00y = bcast2(-u0.y);
        ull u01x = bcast2(u1.x), u01y = bcast2(u1.y), n01y = bcast2(-u1.y);
        ull u10x = bcast2(u2.x), u10y = bcast2(u2.y), n10y = bcast2(-u2.y);
        ull u11x = bcast2(u3.x), u11y = bcast2(u3.y), n11y = bcast2(-u3.y);
#pragma unroll
        for (int k = 0; k < 16; ++k) {
            if (k & (1 << m)) continue;
            int k1 = k | (1 << m);
            ull ar = vr[k], ai = vi[k], br = vr[k1], bi = vi[k1];
            vr[k]  = fma2(u00x, ar, fma2(n00y, ai, fma2(u01x, br, mul2(n01y, bi))));
            vi[k]  = fma2(u00x, ai, fma2(u00y, ar, fma2(u01x, bi, mul2(u01y, br))));
            vr[k1] = fma2(u10x, ar, fma2(n10y, ai, fma2(u11x, br, mul2(n11y, bi))));
            vi[k1] = fma2(u10x, ai, fma2(u10y, ar, fma2(u11x, bi, mul2(u11y, br))));
        }
    }
#pragma unroll
    for (int k = 0; k < 16; ++k) {
        int idx = base + k * stride;
        int j = GRAY ? grayinv(idx) : idx;
        int pn = padidx(j);
        sre[pn] = vr[k]; sim[pn] = vi[k];
    }
}

__global__ __launch_bounds__(NTHREADS, 2)
void qnn_kernel(const float* __restrict__ x, float* __restrict__ out, int B)
{
    extern __shared__ ull smembuf[];
    ull* sre = smembuf;            // PADDED packed re
    ull* sim = smembuf + PADDED;   // PADDED packed im

    __shared__ float2 sU[3][12][4];
    __shared__ ull scw2[NQ], ssw2[NQ];

    const int tid = threadIdx.x;
    const int b0 = 2 * blockIdx.x;
    const int b1 = (b0 + 1 < B) ? b0 + 1 : b0;

    if (tid < NQ) {
        float sa, ca; sincosf(0.5f * x[b0 * NQ + tid], &sa, &ca);
        float sb, cb; sincosf(0.5f * x[b1 * NQ + tid], &sb, &cb);
        scw2[tid] = pack2(ca, cb);
        ssw2[tid] = pack2(sa, sb);
    }
    if (tid < 3 * 12 * 4) ((float2*)sU)[tid] = ((const float2*)g_U)[tid];
    __syncthreads();

    ull vr[16], vi[16];

    // ---- layer 0, pass 1: build initial product state directly in the
    // pass-1 register layout (idx = tid*16 + k), then apply gates on bits 0..3.
    {
        // idx bits 4..11 = tid bits 0..7; bit p <-> wire 11-p.
        // wires 0..7 come from tid: bit for wire w is (tid >> (7-w)) & 1.
        ull phi = scw2[0];
        if ((tid >> 7) & 1) phi = ssw2[0];
#pragma unroll
        for (int w = 1; w < 8; ++w)
            phi = mul2(phi, ((tid >> (7 - w)) & 1) ? ssw2[w] : scw2[w]);
        // k bits: p=0 -> wire 11, p=1 -> wire 10, p=2 -> wire 9, p=3 -> wire 8
        ull lo[4], hi[4];
#pragma unroll
        for (int a = 0; a < 4; ++a)
            lo[a] = mul2((a & 1) ? ssw2[11] : scw2[11],
                         (a & 2) ? ssw2[10] : scw2[10]);
#pragma unroll
        for (int bq = 0; bq < 4; ++bq)
            hi[bq] = mul2(phi, mul2((bq & 1) ? ssw2[9] : scw2[9],
                                    (bq & 2) ? ssw2[8] : scw2[8]));
#pragma unroll
        for (int k = 0; k < 16; ++k) {
            vr[k] = mul2(hi[(k >> 2) & 3], lo[k & 3]);
            vi[k] = 0ULL;   // (0.0f, 0.0f)
        }
        gate_pass<false, false>(sre, sim, sU[0], tid << 4, 1, 0, vr, vi);
    }
    __syncthreads();
    gate_pass<true, false>(sre, sim, sU[0], (tid & 15) | ((tid >> 4) << 8), 16, 4, vr, vi);
    __syncthreads();
    gate_pass<true, true >(sre, sim, sU[0], tid, 256, 8, vr, vi);
    __syncthreads();

#pragma unroll 1
    for (int layer = 1; layer < 3; ++layer) {
        gate_pass<true, false>(sre, sim, sU[layer], tid << 4, 1, 0, vr, vi);
        __syncthreads();
        gate_pass<true, false>(sre, sim, sU[layer], (tid & 15) | ((tid >> 4) << 8), 16, 4, vr, vi);
        __syncthreads();
        gate_pass<true, true >(sre, sim, sU[layer], tid, 256, 8, vr, vi);
        __syncthreads();
    }

    if (tid == 0) {
        float r0a, r0b, i0a, i0b, r1a, r1b, i1a, i1b;
        unpack2(sre[padidx(0)], r0a, r0b);
        unpack2(sim[padidx(0)], i0a, i0b);
        unpack2(sre[padidx(1)], r1a, r1b);
        unpack2(sim[padidx(1)], i1a, i1b);
        {
            float p0 = r0a * r0a + i0a * i0a;
            float p1 = r1a * r1a + i1a * i1a;
            float inv = 1.0f / (p0 + p1);
            out[b0 * 2 + 0] = p0 * inv;
            out[b0 * 2 + 1] = p1 * inv;
        }
        if (b1 != b0) {
            float p0 = r0b * r0b + i0b * i0b;
            float p1 = r1b * r1b + i1b * i1b;
            float inv = 1.0f / (p0 + p1);
            out[b1 * 2 + 0] = p0 * inv;
            out[b1 * 2 + 1] = p1 * inv;
        }
    }
}

extern "C" void kernel_launch(void* const* d_in, const int* in_sizes, int n_in,
                              void* d_out, int out_size) {
    const float* x      = (const float*)d_in[0];  // (B, 12) float32
    const float* params = (const float*)d_in[1];  // (3, 12, 3) float32
    float* out = (float*)d_out;                   // (B, 2) float32
    int B = in_sizes[0] / NQ;
    int grid = (B + 1) / 2;

    size_t shbytes = 2ull * PADDED * sizeof(ull);   // 69632 bytes
    static bool attr_done = false;
    if (!attr_done) {
        cudaFuncSetAttribute(qnn_kernel,
                             cudaFuncAttributeMaxDynamicSharedMemorySize,
                             (int)shbytes);
        attr_done = true;
    }

    precompute_U_kernel<<<1, 64>>>(params);
    qnn_kernel<<<grid, NTHREADS, shbytes>>>(x, out, B);
}